// round 2
// baseline (speedup 1.0000x reference)
#include <cuda_runtime.h>
#include <math.h>

// Problem constants (fixed by the reference)
#define N_NODES 50000
#define N_EDGES 800000
#define IN_DIM  128
#define H_DIM   128
#define OUT_DIM 64
#define H1_DIM  512
#define EW_BLOCKS ((N_EDGES * 16 + 255) / 256)   // 50000

// alpha = 0.0 in reference -> x0/conv_w2 terms vanish.
#define BETA0 0.6931471805599453f   /* ln(2)   */
#define BETA1 0.4054651081081644f   /* ln(1.5) */

// ---------------- device scratch (static globals; no cudaMalloc allowed) ----
__device__ float  g_h1[N_NODES * H1_DIM];
__device__ float  g_h2[N_NODES * OUT_DIM];
__device__ float  g_glp[N_NODES * 128];   // [logits | lp] interleaved per row
__device__ float  g_P[OUT_DIM * OUT_DIM];
__device__ float  g_Wcat[OUT_DIM * 128];  // [w3 | w3@P]
__device__ float  g_bcat[128];            // [b3 | b3@P]
__device__ float  g_hA[N_NODES * H_DIM];
__device__ float  g_hB[N_NODES * H_DIM];
__device__ float  g_agg[N_NODES * H_DIM];
__device__ float  g_ewraw[N_EDGES];
__device__ float  g_ewp[N_EDGES];
__device__ float  g_normw[N_EDGES];
__device__ int    g_esrc[N_EDGES];
__device__ int    g_cnt[N_NODES];
__device__ int    g_cursor[N_NODES];
__device__ int    g_rowptr[N_NODES + 1];
__device__ double g_psum[EW_BLOCKS];
__device__ double g_psum2[EW_BLOCKS];
__device__ float  g_stats[2];
__device__ float  g_dinv[N_NODES];

// ---------------- high-throughput fp32 GEMM -------------------------------
// BM=128, BN=64*TNQ, BK=8, 256 threads, per-thread 8 x (4*TNQ) in quadrants.
// Double-buffered smem, single __syncthreads per K-tile.
// C = relu?( alpha*(A@B) + bias + addA*A )   (addA path requires N==K)
template<int TNQ>
__global__ __launch_bounds__(256, 2)
void gemm2_kernel(const float* __restrict__ A, const float* __restrict__ B,
                  const float* __restrict__ bias, float* __restrict__ C,
                  int M, int N, int K, float alpha, float addA, int do_relu)
{
    __shared__ float As[2][8][132];        // padded: conflict-free scalar stores
    __shared__ float Bs[2][8][64 * TNQ];
    const int tid = threadIdx.x;
    const int tx = tid & 15, ty = tid >> 4;
    const int m0 = blockIdx.x * 128, n0 = blockIdx.y * 64 * TNQ;

    // A tile load: 128 rows x 8 cols = 1024 floats; one float4 per thread.
    const int arow = tid >> 1;
    const int ak   = (tid & 1) * 4;
    const bool avalid = (m0 + arow) < M;
    const float* Ap = A + (size_t)(m0 + arow) * K + ak;

    // B tile load: 8 rows x BN cols; float4 (TNQ=2) or float2 (TNQ=1) per thread.
    const int brow = tid >> 5;
    const int bcol = (tid & 31) * (TNQ == 2 ? 4 : 2);
    const float* Bp = B + (size_t)brow * N + n0 + bcol;

    float acc[2][TNQ][4][4];
#pragma unroll
    for (int a = 0; a < 2; a++)
#pragma unroll
        for (int b = 0; b < TNQ; b++)
#pragma unroll
            for (int i = 0; i < 4; i++)
#pragma unroll
                for (int j = 0; j < 4; j++) acc[a][b][i][j] = 0.f;

    float4 apf = avalid ? *(const float4*)Ap : make_float4(0.f, 0.f, 0.f, 0.f);
    float4 bpf4;
    float2 bpf2;
    if (TNQ == 2) bpf4 = *(const float4*)Bp; else bpf2 = *(const float2*)Bp;

    const int ntiles = K >> 3;
    As[0][ak + 0][arow] = apf.x; As[0][ak + 1][arow] = apf.y;
    As[0][ak + 2][arow] = apf.z; As[0][ak + 3][arow] = apf.w;
    if (TNQ == 2) *(float4*)&Bs[0][brow][bcol] = bpf4;
    else          *(float2*)&Bs[0][brow][bcol] = bpf2;
    __syncthreads();

    for (int t = 0; t < ntiles; t++) {
        const int cur = t & 1;
        const bool more = (t + 1) < ntiles;
        if (more) {
            apf = avalid ? *(const float4*)(Ap + (t + 1) * 8)
                         : make_float4(0.f, 0.f, 0.f, 0.f);
            if (TNQ == 2) bpf4 = *(const float4*)(Bp + (size_t)(t + 1) * 8 * N);
            else          bpf2 = *(const float2*)(Bp + (size_t)(t + 1) * 8 * N);
        }
#pragma unroll
        for (int kk = 0; kk < 8; kk++) {
            float4 a0 = *(const float4*)&As[cur][kk][ty * 4];
            float4 a1 = *(const float4*)&As[cur][kk][64 + ty * 4];
            float av[2][4] = {{a0.x, a0.y, a0.z, a0.w}, {a1.x, a1.y, a1.z, a1.w}};
            float bv[TNQ][4];
            float4 b0 = *(const float4*)&Bs[cur][kk][tx * 4];
            bv[0][0] = b0.x; bv[0][1] = b0.y; bv[0][2] = b0.z; bv[0][3] = b0.w;
            if (TNQ == 2) {
                float4 b1 = *(const float4*)&Bs[cur][kk][64 + tx * 4];
                bv[1][0] = b1.x; bv[1][1] = b1.y; bv[1][2] = b1.z; bv[1][3] = b1.w;
            }
#pragma unroll
            for (int mq = 0; mq < 2; mq++)
#pragma unroll
                for (int i = 0; i < 4; i++)
#pragma unroll
                    for (int nq = 0; nq < TNQ; nq++)
#pragma unroll
                        for (int j = 0; j < 4; j++)
                            acc[mq][nq][i][j] += av[mq][i] * bv[nq][j];
        }
        if (more) {
            const int nxt = cur ^ 1;
            As[nxt][ak + 0][arow] = apf.x; As[nxt][ak + 1][arow] = apf.y;
            As[nxt][ak + 2][arow] = apf.z; As[nxt][ak + 3][arow] = apf.w;
            if (TNQ == 2) *(float4*)&Bs[nxt][brow][bcol] = bpf4;
            else          *(float2*)&Bs[nxt][brow][bcol] = bpf2;
            __syncthreads();
        }
    }

#pragma unroll
    for (int mq = 0; mq < 2; mq++) {
#pragma unroll
        for (int i = 0; i < 4; i++) {
            int gm = m0 + mq * 64 + ty * 4 + i;
            if (gm >= M) continue;
#pragma unroll
            for (int nq = 0; nq < TNQ; nq++) {
                int gn = n0 + nq * 64 + tx * 4;
                float4 v;
                v.x = alpha * acc[mq][nq][i][0];
                v.y = alpha * acc[mq][nq][i][1];
                v.z = alpha * acc[mq][nq][i][2];
                v.w = alpha * acc[mq][nq][i][3];
                if (bias) {
                    float4 bb = *(const float4*)&bias[gn];
                    v.x += bb.x; v.y += bb.y; v.z += bb.z; v.w += bb.w;
                }
                if (addA != 0.f) {  // residual: N == K
                    float4 r = *(const float4*)&A[(size_t)gm * K + gn];
                    v.x += addA * r.x; v.y += addA * r.y;
                    v.z += addA * r.z; v.w += addA * r.w;
                }
                if (do_relu) {
                    v.x = fmaxf(v.x, 0.f); v.y = fmaxf(v.y, 0.f);
                    v.z = fmaxf(v.z, 0.f); v.w = fmaxf(v.w, 0.f);
                }
                *(float4*)&C[(size_t)gm * N + gn] = v;
            }
        }
    }
}

// ---------------- P = relu(SCALE * parsing[0]) ----------------
__global__ void p_kernel(const float* __restrict__ parsing)
{
    int i = blockIdx.x * blockDim.x + threadIdx.x;
    if (i < OUT_DIM * OUT_DIM) g_P[i] = fmaxf(2.0f * parsing[i], 0.0f);
}

// ---------------- Wcat = [w3 | w3@P], bcat = [b3 | b3@P] --------------------
__global__ void wcat_kernel(const float* __restrict__ w3, const float* __restrict__ b3)
{
    int idx = blockIdx.x * 256 + threadIdx.x;
    if (idx < 64 * 64) {
        int k = idx >> 6, j = idx & 63;
        g_Wcat[k * 128 + j] = w3[k * 64 + j];
        float s = 0.f;
        for (int i = 0; i < 64; i++) s += w3[k * 64 + i] * g_P[i * 64 + j];
        g_Wcat[k * 128 + 64 + j] = s;
    } else if (idx < 64 * 64 + 64) {
        int j = idx - 64 * 64;
        g_bcat[j] = b3[j];
        float s = 0.f;
        for (int i = 0; i < 64; i++) s += b3[i] * g_P[i * 64 + j];
        g_bcat[64 + j] = s;
    }
}

// ---------------- edge weights: ew[e] = dot(logits[row[e]], lp[col[e]]) ------
__global__ void ew_kernel(const int* __restrict__ erow, const int* __restrict__ ecol)
{
    int t = blockIdx.x * 256 + threadIdx.x;
    int e = t >> 4;
    int l = t & 15;
    float v = 0.f;
    if (e < N_EDGES) {
        int r = erow[e], c = ecol[e];
        float4 a = *(const float4*)(g_glp + (size_t)r * 128 + l * 4);
        float4 b = *(const float4*)(g_glp + (size_t)c * 128 + 64 + l * 4);
        v = a.x * b.x + a.y * b.y + a.z * b.z + a.w * b.w;
    }
#pragma unroll
    for (int off = 8; off > 0; off >>= 1)
        v += __shfl_xor_sync(0xffffffffu, v, off);
    if (l == 0 && e < N_EDGES) g_ewraw[e] = v;

    double s  = (l == 0 && e < N_EDGES) ? (double)v : 0.0;
    double s2 = (l == 0 && e < N_EDGES) ? (double)v * (double)v : 0.0;
    __shared__ double sh1[256];
    __shared__ double sh2[256];
    sh1[threadIdx.x] = s; sh2[threadIdx.x] = s2;
    __syncthreads();
    for (int off = 128; off > 0; off >>= 1) {
        if (threadIdx.x < off) {
            sh1[threadIdx.x] += sh1[threadIdx.x + off];
            sh2[threadIdx.x] += sh2[threadIdx.x + off];
        }
        __syncthreads();
    }
    if (threadIdx.x == 0) { g_psum[blockIdx.x] = sh1[0]; g_psum2[blockIdx.x] = sh2[0]; }
}

__global__ void stats_kernel()
{
    int t = threadIdx.x;
    double s = 0.0, s2 = 0.0;
    for (int i = t; i < EW_BLOCKS; i += 1024) { s += g_psum[i]; s2 += g_psum2[i]; }
    __shared__ double sh1[1024];
    __shared__ double sh2[1024];
    sh1[t] = s; sh2[t] = s2;
    __syncthreads();
    for (int off = 512; off > 0; off >>= 1) {
        if (t < off) { sh1[t] += sh1[t + off]; sh2[t] += sh2[t + off]; }
        __syncthreads();
    }
    if (t == 0) {
        double sum = sh1[0], sumsq = sh2[0];
        double mean = sum / (double)N_EDGES;
        double var = (sumsq - sum * sum / (double)N_EDGES) / (double)(N_EDGES - 1);
        g_stats[0] = (float)mean;
        g_stats[1] = (float)sqrt(1e-4 / var);
    }
}

// ---------------- CSR build (sorted by destination col) ----------------------
__global__ void count_kernel(const int* __restrict__ ecol)
{
    int e = blockIdx.x * blockDim.x + threadIdx.x;
    if (e < N_EDGES) atomicAdd(&g_cnt[ecol[e]], 1);
}

__global__ void scan_kernel()
{
    __shared__ int sh[1024];
    __shared__ int s_carry;
    int t = threadIdx.x;
    if (t == 0) { s_carry = 0; g_rowptr[0] = 0; }
    __syncthreads();
    for (int base = 0; base < N_NODES; base += 1024) {
        int v = (base + t < N_NODES) ? g_cnt[base + t] : 0;
        sh[t] = v;
        __syncthreads();
        for (int off = 1; off < 1024; off <<= 1) {
            int add = (t >= off) ? sh[t - off] : 0;
            __syncthreads();
            sh[t] += add;
            __syncthreads();
        }
        int inc = sh[t] + s_carry;
        if (base + t < N_NODES) {
            g_rowptr[base + t + 1] = inc;
            g_cursor[base + t] = inc - v;
        }
        int total = sh[1023];
        __syncthreads();
        if (t == 0) s_carry += total;
        __syncthreads();
    }
}

__global__ void scatter_kernel(const int* __restrict__ erow, const int* __restrict__ ecol)
{
    int e = blockIdx.x * blockDim.x + threadIdx.x;
    if (e < N_EDGES) {
        int p = atomicAdd(&g_cursor[ecol[e]], 1);
        g_esrc[p] = erow[e];
        g_ewp[p] = g_ewraw[e];
    }
}

__global__ void deg_kernel()
{
    int warp = (blockIdx.x * blockDim.x + threadIdx.x) >> 5;
    int lane = threadIdx.x & 31;
    if (warp >= N_NODES) return;
    float mean = g_stats[0], scale = g_stats[1];
    int s0 = g_rowptr[warp], s1 = g_rowptr[warp + 1];
    float s = 0.f;
    for (int p = s0 + lane; p < s1; p += 32) {
        float w = (g_ewp[p] - mean) * scale + 1.0f;
        g_ewp[p] = w;
        s += w;
    }
#pragma unroll
    for (int off = 16; off > 0; off >>= 1)
        s += __shfl_xor_sync(0xffffffffu, s, off);
    if (lane == 0) {
        float deg = s + 1.0f;
        g_dinv[warp] = (deg > 0.f) ? rsqrtf(deg) : 0.f;
    }
}

__global__ void normw_kernel()
{
    int warp = (blockIdx.x * blockDim.x + threadIdx.x) >> 5;
    int lane = threadIdx.x & 31;
    if (warp >= N_NODES) return;
    float di = g_dinv[warp];
    int s0 = g_rowptr[warp], s1 = g_rowptr[warp + 1];
    for (int p = s0 + lane; p < s1; p += 32)
        g_normw[p] = g_dinv[g_esrc[p]] * g_ewp[p] * di;
}

// ---------------- SpMM: agg[n] = sum_in normw*h[src] + dinv[n]^2 * h[n] ------
__global__ void spmm_kernel(const float* __restrict__ hin, float* __restrict__ agg)
{
    int warp = (blockIdx.x * blockDim.x + threadIdx.x) >> 5;
    int lane = threadIdx.x & 31;
    if (warp >= N_NODES) return;
    const float4* h4 = (const float4*)hin;
    float di = g_dinv[warp];
    float selfw = di * di;
    float4 hv = h4[(size_t)warp * 32 + lane];
    float4 acc;
    acc.x = selfw * hv.x; acc.y = selfw * hv.y; acc.z = selfw * hv.z; acc.w = selfw * hv.w;
    int s0 = g_rowptr[warp], s1 = g_rowptr[warp + 1];
    for (int p = s0; p < s1; p++) {
        float w = g_normw[p];
        int src = g_esrc[p];
        float4 v = h4[(size_t)src * 32 + lane];
        acc.x += w * v.x; acc.y += w * v.y; acc.z += w * v.z; acc.w += w * v.w;
    }
    ((float4*)agg)[(size_t)warp * 32 + lane] = acc;
}

// ---------------- launch ----------------------------------------------------
extern "C" void kernel_launch(void* const* d_in, const int* in_sizes, int n_in,
                              void* d_out, int out_size)
{
    const float* x       = (const float*)d_in[0];
    const int*   eidx    = (const int*)d_in[1];
    const float* w1      = (const float*)d_in[2];
    const float* b1      = (const float*)d_in[3];
    const float* w2      = (const float*)d_in[4];
    const float* b2      = (const float*)d_in[5];
    const float* w3      = (const float*)d_in[6];
    const float* b3      = (const float*)d_in[7];
    const float* parsing = (const float*)d_in[8];
    const float* l0w     = (const float*)d_in[9];
    const float* l0b     = (const float*)d_in[10];
    const float* l1w     = (const float*)d_in[11];
    const float* l1b     = (const float*)d_in[12];
    const float* cw1     = (const float*)d_in[13];
    float* out = (float*)d_out;
    const int* erow = eidx;
    const int* ecol = eidx + N_EDGES;

    float *p_h1, *p_h2, *p_glp, *p_Wcat, *p_bcat, *p_hA, *p_hB, *p_agg;
    int *p_cnt;
    cudaGetSymbolAddress((void**)&p_h1, g_h1);
    cudaGetSymbolAddress((void**)&p_h2, g_h2);
    cudaGetSymbolAddress((void**)&p_glp, g_glp);
    cudaGetSymbolAddress((void**)&p_Wcat, g_Wcat);
    cudaGetSymbolAddress((void**)&p_bcat, g_bcat);
    cudaGetSymbolAddress((void**)&p_hA, g_hA);
    cudaGetSymbolAddress((void**)&p_hB, g_hB);
    cudaGetSymbolAddress((void**)&p_agg, g_agg);
    cudaGetSymbolAddress((void**)&p_cnt, g_cnt);

    const int gmx = (N_NODES + 127) / 128;  // 391

    p_kernel<<<4, 1024>>>(parsing);
    wcat_kernel<<<17, 256>>>(w3, b3);

    // MLP: x -> h1 -> h2 -> [logits | lp]
    gemm2_kernel<2><<<dim3(gmx, 4), 256>>>(x, w1, b1, p_h1, N_NODES, 512, IN_DIM, 1.f, 0.f, 1);
    gemm2_kernel<1><<<dim3(gmx, 1), 256>>>(p_h1, w2, b2, p_h2, N_NODES, OUT_DIM, H1_DIM, 1.f, 0.f, 1);
    gemm2_kernel<2><<<dim3(gmx, 1), 256>>>(p_h2, p_Wcat, p_bcat, p_glp, N_NODES, 128, OUT_DIM, 1.f, 0.f, 0);
    // x0 = relu(x @ lin0 + b)
    gemm2_kernel<2><<<dim3(gmx, 1), 256>>>(x, l0w, l0b, p_hA, N_NODES, H_DIM, IN_DIM, 1.f, 0.f, 1);

    // edge weights + stats
    ew_kernel<<<EW_BLOCKS, 256>>>(erow, ecol);
    stats_kernel<<<1, 1024>>>();

    // CSR build
    cudaMemsetAsync(p_cnt, 0, N_NODES * sizeof(int));
    count_kernel<<<(N_EDGES + 255) / 256, 256>>>(ecol);
    scan_kernel<<<1, 1024>>>();
    scatter_kernel<<<(N_EDGES + 255) / 256, 256>>>(erow, ecol);
    deg_kernel<<<(N_NODES + 7) / 8, 256>>>();
    normw_kernel<<<(N_NODES + 7) / 8, 256>>>();

    // layer 0
    spmm_kernel<<<(N_NODES + 7) / 8, 256>>>(p_hA, p_agg);
    gemm2_kernel<2><<<dim3(gmx, 1), 256>>>(p_agg, cw1, nullptr, p_hB,
                                           N_NODES, H_DIM, H_DIM, BETA0, 1.f - BETA0, 1);
    // layer 1
    spmm_kernel<<<(N_NODES + 7) / 8, 256>>>(p_hB, p_agg);
    gemm2_kernel<2><<<dim3(gmx, 1), 256>>>(p_agg, cw1 + H_DIM * H_DIM, nullptr, p_hA,
                                           N_NODES, H_DIM, H_DIM, BETA1, 1.f - BETA1, 1);
    // output
    gemm2_kernel<1><<<dim3(gmx, 1), 256>>>(p_hA, l1w, l1b, out, N_NODES, OUT_DIM, H_DIM, 1.f, 0.f, 0);
}

// round 3
// speedup vs baseline: 1.8946x; 1.8946x over previous
#include <cuda_runtime.h>
#include <math.h>
#include <stdint.h>

// Problem constants (fixed by the reference)
#define N_NODES 50000
#define N_EDGES 800000
#define IN_DIM  128
#define H_DIM   128
#define OUT_DIM 64
#define H1_DIM  512
#define EW_BLOCKS ((N_EDGES * 16 + 255) / 256)   // 50000

// alpha = 0.0 in reference -> x0/conv_w2 terms vanish.
#define BETA0 0.6931471805599453f   /* ln(2)   */
#define BETA1 0.4054651081081644f   /* ln(1.5) */

// ---------------- device scratch (static globals; no cudaMalloc allowed) ----
__device__ float  g_h1[N_NODES * H1_DIM];
__device__ float  g_h2[N_NODES * OUT_DIM];
__device__ float  g_glp[N_NODES * 128];   // [logits | lp] per row
__device__ float  g_P[OUT_DIM * OUT_DIM];
__device__ float  g_Wcat[OUT_DIM * 128];  // [w3 | w3@P]
__device__ float  g_bcat[128];            // [b3 | b3@P]
__device__ float  g_hA[N_NODES * H_DIM];
__device__ float  g_hB[N_NODES * H_DIM];
__device__ float  g_agg[N_NODES * H_DIM];
__device__ float  g_ewraw[N_EDGES];
__device__ float  g_ewp[N_EDGES];
__device__ float  g_normw[N_EDGES];
__device__ int    g_esrc[N_EDGES];
__device__ int    g_cnt[N_NODES];
__device__ int    g_cursor[N_NODES];
__device__ int    g_rowptr[N_NODES + 1];
__device__ double g_psum[EW_BLOCKS];
__device__ double g_psum2[EW_BLOCKS];
__device__ float  g_stats[2];
__device__ float  g_dinv[N_NODES];

// ---------------- tf32 tensor-core GEMM ------------------------------------
// C = relu?( alpha*(A@B) + bias + addA*A )   (addA path requires N==K)
// Block tile 128x64, 8 warps in 4x2; warp tile 32x32 = 2x4 m16n8k8 mmas.
// BK=16, double-buffered smem, padded strides for conflict-free frag loads.

__device__ __forceinline__ uint32_t f2tf32(float f)
{
    uint32_t o;
    asm("cvt.rna.tf32.f32 %0, %1;" : "=r"(o) : "f"(f));
    return o;
}

__device__ __forceinline__ void mma_tf32(float d[4], const uint32_t a[4], const uint32_t b[2])
{
    asm volatile(
        "mma.sync.aligned.m16n8k8.row.col.f32.tf32.tf32.f32 "
        "{%0,%1,%2,%3}, {%4,%5,%6,%7}, {%8,%9}, {%0,%1,%2,%3};"
        : "+f"(d[0]), "+f"(d[1]), "+f"(d[2]), "+f"(d[3])
        : "r"(a[0]), "r"(a[1]), "r"(a[2]), "r"(a[3]), "r"(b[0]), "r"(b[1]));
}

#define AS_STRIDE 136   // 136 % 32 == 8 -> frag loads hit 32 distinct banks
#define BS_STRIDE 72    // 72  % 32 == 8

__global__ __launch_bounds__(256, 2)
void gemm_tc(const float* __restrict__ A, const float* __restrict__ B,
             const float* __restrict__ bias, float* __restrict__ C,
             int M, int N, int K, float alpha, float addA, int do_relu)
{
    __shared__ uint32_t As[2][16][AS_STRIDE];   // [k][m], tf32 bits
    __shared__ uint32_t Bs[2][16][BS_STRIDE];   // [k][n], tf32 bits

    const int tid  = threadIdx.x;
    const int lane = tid & 31;
    const int wid  = tid >> 5;
    const int wm   = wid & 3;        // warp m index (0..3) -> 32-row slab
    const int wn   = wid >> 2;       // warp n index (0..1) -> 32-col slab
    const int gid  = lane >> 2;      // groupID 0..7
    const int tig  = lane & 3;       // threadID_in_group 0..3
    const int m0   = blockIdx.x * 128;
    const int n0   = blockIdx.y * 64;

    // Global A tile loads: 128 rows x 16 k; thread -> row=tid>>1, kq=(tid&1)*8.
    const int arow = tid >> 1;
    const int akq  = (tid & 1) * 8;
    const bool av  = (m0 + arow) < M;
    const float* Ap = A + (size_t)(m0 + arow) * K + akq;
    // Global B tile loads: 16 k x 64 n; thread -> k=tid>>4, n=(tid&15)*4.
    const int bk = tid >> 4;
    const int bn = (tid & 15) * 4;
    const float* Bp = B + (size_t)bk * N + n0 + bn;

    float d[2][4][4];
#pragma unroll
    for (int f = 0; f < 2; f++)
#pragma unroll
        for (int g = 0; g < 4; g++)
#pragma unroll
            for (int i = 0; i < 4; i++) d[f][g][i] = 0.f;

    const int ntiles = K >> 4;
    const float4 z4 = make_float4(0.f, 0.f, 0.f, 0.f);

    float4 a4a = av ? *(const float4*)Ap : z4;
    float4 a4b = av ? *(const float4*)(Ap + 4) : z4;
    float4 b4  = *(const float4*)Bp;

    // store tile 0
    As[0][akq + 0][arow] = f2tf32(a4a.x); As[0][akq + 1][arow] = f2tf32(a4a.y);
    As[0][akq + 2][arow] = f2tf32(a4a.z); As[0][akq + 3][arow] = f2tf32(a4a.w);
    As[0][akq + 4][arow] = f2tf32(a4b.x); As[0][akq + 5][arow] = f2tf32(a4b.y);
    As[0][akq + 6][arow] = f2tf32(a4b.z); As[0][akq + 7][arow] = f2tf32(a4b.w);
    Bs[0][bk][bn + 0] = f2tf32(b4.x); Bs[0][bk][bn + 1] = f2tf32(b4.y);
    Bs[0][bk][bn + 2] = f2tf32(b4.z); Bs[0][bk][bn + 3] = f2tf32(b4.w);
    __syncthreads();

    for (int t = 0; t < ntiles; t++) {
        const int cur = t & 1;
        const bool more = (t + 1) < ntiles;
        if (more) {
            const float* Apn = Ap + (t + 1) * 16;
            a4a = av ? *(const float4*)Apn : z4;
            a4b = av ? *(const float4*)(Apn + 4) : z4;
            b4 = *(const float4*)(Bp + (size_t)(t + 1) * 16 * N);
        }
#pragma unroll
        for (int ks = 0; ks < 16; ks += 8) {
            uint32_t af[2][4];
#pragma unroll
            for (int f = 0; f < 2; f++) {
                const int rb = wm * 32 + f * 16;
                af[f][0] = As[cur][ks + tig][rb + gid];
                af[f][1] = As[cur][ks + tig][rb + gid + 8];
                af[f][2] = As[cur][ks + tig + 4][rb + gid];
                af[f][3] = As[cur][ks + tig + 4][rb + gid + 8];
            }
            uint32_t bf[4][2];
#pragma unroll
            for (int g = 0; g < 4; g++) {
                const int nb = wn * 32 + g * 8;
                bf[g][0] = Bs[cur][ks + tig][nb + gid];
                bf[g][1] = Bs[cur][ks + tig + 4][nb + gid];
            }
#pragma unroll
            for (int f = 0; f < 2; f++)
#pragma unroll
                for (int g = 0; g < 4; g++)
                    mma_tf32(d[f][g], af[f], bf[g]);
        }
        if (more) {
            const int nxt = cur ^ 1;
            As[nxt][akq + 0][arow] = f2tf32(a4a.x); As[nxt][akq + 1][arow] = f2tf32(a4a.y);
            As[nxt][akq + 2][arow] = f2tf32(a4a.z); As[nxt][akq + 3][arow] = f2tf32(a4a.w);
            As[nxt][akq + 4][arow] = f2tf32(a4b.x); As[nxt][akq + 5][arow] = f2tf32(a4b.y);
            As[nxt][akq + 6][arow] = f2tf32(a4b.z); As[nxt][akq + 7][arow] = f2tf32(a4b.w);
            Bs[nxt][bk][bn + 0] = f2tf32(b4.x); Bs[nxt][bk][bn + 1] = f2tf32(b4.y);
            Bs[nxt][bk][bn + 2] = f2tf32(b4.z); Bs[nxt][bk][bn + 3] = f2tf32(b4.w);
            __syncthreads();
        }
    }

    // epilogue: c0,c1 -> (row, col..col+1); c2,c3 -> (row+8, ...)
#pragma unroll
    for (int f = 0; f < 2; f++) {
        const int r0 = m0 + wm * 32 + f * 16 + gid;
#pragma unroll
        for (int g = 0; g < 4; g++) {
            const int cc = n0 + wn * 32 + g * 8 + 2 * tig;
#pragma unroll
            for (int h = 0; h < 2; h++) {
                const int gm = r0 + h * 8;
                if (gm >= M) continue;
                float v0 = alpha * d[f][g][2 * h + 0];
                float v1 = alpha * d[f][g][2 * h + 1];
                if (bias) {
                    float2 bb = *(const float2*)&bias[cc];
                    v0 += bb.x; v1 += bb.y;
                }
                if (addA != 0.f) {  // residual path: N == K
                    float2 r = *(const float2*)&A[(size_t)gm * K + cc];
                    v0 += addA * r.x; v1 += addA * r.y;
                }
                if (do_relu) { v0 = fmaxf(v0, 0.f); v1 = fmaxf(v1, 0.f); }
                *(float2*)&C[(size_t)gm * N + cc] = make_float2(v0, v1);
            }
        }
    }
}

// ---------------- P = relu(SCALE * parsing[0]) ----------------
__global__ void p_kernel(const float* __restrict__ parsing)
{
    int i = blockIdx.x * blockDim.x + threadIdx.x;
    if (i < OUT_DIM * OUT_DIM) g_P[i] = fmaxf(2.0f * parsing[i], 0.0f);
}

// ---------------- Wcat = [w3 | w3@P], bcat = [b3 | b3@P] --------------------
__global__ void wcat_kernel(const float* __restrict__ w3, const float* __restrict__ b3)
{
    int idx = blockIdx.x * 256 + threadIdx.x;
    if (idx < 64 * 64) {
        int k = idx >> 6, j = idx & 63;
        g_Wcat[k * 128 + j] = w3[k * 64 + j];
        float s = 0.f;
        for (int i = 0; i < 64; i++) s += w3[k * 64 + i] * g_P[i * 64 + j];
        g_Wcat[k * 128 + 64 + j] = s;
    } else if (idx < 64 * 64 + 64) {
        int j = idx - 64 * 64;
        g_bcat[j] = b3[j];
        float s = 0.f;
        for (int i = 0; i < 64; i++) s += b3[i] * g_P[i * 64 + j];
        g_bcat[64 + j] = s;
    }
}

// ---------------- edge weights: ew[e] = dot(logits[row[e]], lp[col[e]]) ------
__global__ void ew_kernel(const int* __restrict__ erow, const int* __restrict__ ecol)
{
    int t = blockIdx.x * 256 + threadIdx.x;
    int e = t >> 4;
    int l = t & 15;
    float v = 0.f;
    if (e < N_EDGES) {
        int r = erow[e], c = ecol[e];
        float4 a = *(const float4*)(g_glp + (size_t)r * 128 + l * 4);
        float4 b = *(const float4*)(g_glp + (size_t)c * 128 + 64 + l * 4);
        v = a.x * b.x + a.y * b.y + a.z * b.z + a.w * b.w;
    }
#pragma unroll
    for (int off = 8; off > 0; off >>= 1)
        v += __shfl_xor_sync(0xffffffffu, v, off);
    if (l == 0 && e < N_EDGES) g_ewraw[e] = v;

    double s  = (l == 0 && e < N_EDGES) ? (double)v : 0.0;
    double s2 = (l == 0 && e < N_EDGES) ? (double)v * (double)v : 0.0;
    __shared__ double sh1[256];
    __shared__ double sh2[256];
    sh1[threadIdx.x] = s; sh2[threadIdx.x] = s2;
    __syncthreads();
    for (int off = 128; off > 0; off >>= 1) {
        if (threadIdx.x < off) {
            sh1[threadIdx.x] += sh1[threadIdx.x + off];
            sh2[threadIdx.x] += sh2[threadIdx.x + off];
        }
        __syncthreads();
    }
    if (threadIdx.x == 0) { g_psum[blockIdx.x] = sh1[0]; g_psum2[blockIdx.x] = sh2[0]; }
}

__global__ void stats_kernel()
{
    int t = threadIdx.x;
    double s = 0.0, s2 = 0.0;
    for (int i = t; i < EW_BLOCKS; i += 1024) { s += g_psum[i]; s2 += g_psum2[i]; }
    __shared__ double sh1[1024];
    __shared__ double sh2[1024];
    sh1[t] = s; sh2[t] = s2;
    __syncthreads();
    for (int off = 512; off > 0; off >>= 1) {
        if (t < off) { sh1[t] += sh1[t + off]; sh2[t] += sh2[t + off]; }
        __syncthreads();
    }
    if (t == 0) {
        double sum = sh1[0], sumsq = sh2[0];
        double mean = sum / (double)N_EDGES;
        double var = (sumsq - sum * sum / (double)N_EDGES) / (double)(N_EDGES - 1);
        g_stats[0] = (float)mean;
        g_stats[1] = (float)sqrt(1e-4 / var);
    }
}

// ---------------- CSR build (sorted by destination col) ----------------------
__global__ void count_kernel(const int* __restrict__ ecol)
{
    int e = blockIdx.x * blockDim.x + threadIdx.x;
    if (e < N_EDGES) atomicAdd(&g_cnt[ecol[e]], 1);
}

__global__ void scan_kernel()
{
    __shared__ int sh[1024];
    __shared__ int s_carry;
    int t = threadIdx.x;
    if (t == 0) { s_carry = 0; g_rowptr[0] = 0; }
    __syncthreads();
    for (int base = 0; base < N_NODES; base += 1024) {
        int v = (base + t < N_NODES) ? g_cnt[base + t] : 0;
        sh[t] = v;
        __syncthreads();
        for (int off = 1; off < 1024; off <<= 1) {
            int add = (t >= off) ? sh[t - off] : 0;
            __syncthreads();
            sh[t] += add;
            __syncthreads();
        }
        int inc = sh[t] + s_carry;
        if (base + t < N_NODES) {
            g_rowptr[base + t + 1] = inc;
            g_cursor[base + t] = inc - v;
        }
        int total = sh[1023];
        __syncthreads();
        if (t == 0) s_carry += total;
        __syncthreads();
    }
}

__global__ void scatter_kernel(const int* __restrict__ erow, const int* __restrict__ ecol)
{
    int e = blockIdx.x * blockDim.x + threadIdx.x;
    if (e < N_EDGES) {
        int p = atomicAdd(&g_cursor[ecol[e]], 1);
        g_esrc[p] = erow[e];
        g_ewp[p] = g_ewraw[e];
    }
}

__global__ void deg_kernel()
{
    int warp = (blockIdx.x * blockDim.x + threadIdx.x) >> 5;
    int lane = threadIdx.x & 31;
    if (warp >= N_NODES) return;
    float mean = g_stats[0], scale = g_stats[1];
    int s0 = g_rowptr[warp], s1 = g_rowptr[warp + 1];
    float s = 0.f;
    for (int p = s0 + lane; p < s1; p += 32) {
        float w = (g_ewp[p] - mean) * scale + 1.0f;
        g_ewp[p] = w;
        s += w;
    }
#pragma unroll
    for (int off = 16; off > 0; off >>= 1)
        s += __shfl_xor_sync(0xffffffffu, s, off);
    if (lane == 0) {
        float deg = s + 1.0f;
        g_dinv[warp] = (deg > 0.f) ? rsqrtf(deg) : 0.f;
    }
}

__global__ void normw_kernel()
{
    int warp = (blockIdx.x * blockDim.x + threadIdx.x) >> 5;
    int lane = threadIdx.x & 31;
    if (warp >= N_NODES) return;
    float di = g_dinv[warp];
    int s0 = g_rowptr[warp], s1 = g_rowptr[warp + 1];
    for (int p = s0 + lane; p < s1; p += 32)
        g_normw[p] = g_dinv[g_esrc[p]] * g_ewp[p] * di;
}

// ---------------- SpMM: agg[n] = sum_in normw*h[src] + dinv[n]^2 * h[n] ------
__global__ void spmm_kernel(const float* __restrict__ hin, float* __restrict__ agg)
{
    int warp = (blockIdx.x * blockDim.x + threadIdx.x) >> 5;
    int lane = threadIdx.x & 31;
    if (warp >= N_NODES) return;
    const float4* h4 = (const float4*)hin;
    float di = g_dinv[warp];
    float selfw = di * di;
    float4 hv = h4[(size_t)warp * 32 + lane];
    float4 acc;
    acc.x = selfw * hv.x; acc.y = selfw * hv.y; acc.z = selfw * hv.z; acc.w = selfw * hv.w;
    int s0 = g_rowptr[warp], s1 = g_rowptr[warp + 1];
    for (int p = s0; p < s1; p++) {
        float w = g_normw[p];
        int src = g_esrc[p];
        float4 v = h4[(size_t)src * 32 + lane];
        acc.x += w * v.x; acc.y += w * v.y; acc.z += w * v.z; acc.w += w * v.w;
    }
    ((float4*)agg)[(size_t)warp * 32 + lane] = acc;
}

// ---------------- launch ----------------------------------------------------
extern "C" void kernel_launch(void* const* d_in, const int* in_sizes, int n_in,
                              void* d_out, int out_size)
{
    const float* x       = (const float*)d_in[0];
    const int*   eidx    = (const int*)d_in[1];
    const float* w1      = (const float*)d_in[2];
    const float* b1      = (const float*)d_in[3];
    const float* w2      = (const float*)d_in[4];
    const float* b2      = (const float*)d_in[5];
    const float* w3      = (const float*)d_in[6];
    const float* b3      = (const float*)d_in[7];
    const float* parsing = (const float*)d_in[8];
    const float* l0w     = (const float*)d_in[9];
    const float* l0b     = (const float*)d_in[10];
    const float* l1w     = (const float*)d_in[11];
    const float* l1b     = (const float*)d_in[12];
    const float* cw1     = (const float*)d_in[13];
    float* out = (float*)d_out;
    const int* erow = eidx;
    const int* ecol = eidx + N_EDGES;

    float *p_h1, *p_h2, *p_glp, *p_Wcat, *p_bcat, *p_hA, *p_hB, *p_agg;
    int *p_cnt;
    cudaGetSymbolAddress((void**)&p_h1, g_h1);
    cudaGetSymbolAddress((void**)&p_h2, g_h2);
    cudaGetSymbolAddress((void**)&p_glp, g_glp);
    cudaGetSymbolAddress((void**)&p_Wcat, g_Wcat);
    cudaGetSymbolAddress((void**)&p_bcat, g_bcat);
    cudaGetSymbolAddress((void**)&p_hA, g_hA);
    cudaGetSymbolAddress((void**)&p_hB, g_hB);
    cudaGetSymbolAddress((void**)&p_agg, g_agg);
    cudaGetSymbolAddress((void**)&p_cnt, g_cnt);

    const int gmx = (N_NODES + 127) / 128;  // 391

    p_kernel<<<4, 1024>>>(parsing);
    wcat_kernel<<<17, 256>>>(w3, b3);

    // MLP: x -> h1 -> h2 -> [logits | lp]
    gemm_tc<<<dim3(gmx, 8), 256>>>(x, w1, b1, p_h1, N_NODES, 512, IN_DIM, 1.f, 0.f, 1);
    gemm_tc<<<dim3(gmx, 1), 256>>>(p_h1, w2, b2, p_h2, N_NODES, OUT_DIM, H1_DIM, 1.f, 0.f, 1);
    gemm_tc<<<dim3(gmx, 2), 256>>>(p_h2, p_Wcat, p_bcat, p_glp, N_NODES, 128, OUT_DIM, 1.f, 0.f, 0);
    // x0 = relu(x @ lin0 + b)
    gemm_tc<<<dim3(gmx, 2), 256>>>(x, l0w, l0b, p_hA, N_NODES, H_DIM, IN_DIM, 1.f, 0.f, 1);

    // edge weights + stats
    ew_kernel<<<EW_BLOCKS, 256>>>(erow, ecol);
    stats_kernel<<<1, 1024>>>();

    // CSR build
    cudaMemsetAsync(p_cnt, 0, N_NODES * sizeof(int));
    count_kernel<<<(N_EDGES + 255) / 256, 256>>>(ecol);
    scan_kernel<<<1, 1024>>>();
    scatter_kernel<<<(N_EDGES + 255) / 256, 256>>>(erow, ecol);
    deg_kernel<<<(N_NODES + 7) / 8, 256>>>();
    normw_kernel<<<(N_NODES + 7) / 8, 256>>>();

    // layer 0
    spmm_kernel<<<(N_NODES + 7) / 8, 256>>>(p_hA, p_agg);
    gemm_tc<<<dim3(gmx, 2), 256>>>(p_agg, cw1, nullptr, p_hB,
                                   N_NODES, H_DIM, H_DIM, BETA0, 1.f - BETA0, 1);
    // layer 1
    spmm_kernel<<<(N_NODES + 7) / 8, 256>>>(p_hB, p_agg);
    gemm_tc<<<dim3(gmx, 2), 256>>>(p_agg, cw1 + H_DIM * H_DIM, nullptr, p_hA,
                                   N_NODES, H_DIM, H_DIM, BETA1, 1.f - BETA1, 1);
    // output
    gemm_tc<<<dim3(gmx, 1), 256>>>(p_hA, l1w, l1b, out, N_NODES, OUT_DIM, H_DIM, 1.f, 0.f, 0);
}